// round 4
// baseline (speedup 1.0000x reference)
#include <cuda_runtime.h>

#define NSEQ 1024
#define CH   64
#define NPTS (2 * NSEQ)

// Scratch (allocation-free rule: __device__ globals)
__device__ float g_Ui [NPTS * CH];  //  |w2h|*(y+b1), channel-permuted (P group first)
__device__ float g_Ujn[NPTS * CH];  // -|w2h|*y,      channel-permuted
__device__ int   g_cp;              // # channels with w2 >= 0

// ---------------------------------------------------------------------------
// K1: y[p][o] = sum_c W1[o][c] * x[p][c]
//     Ui[p][perm(o)]  =  |w2[o]|/2 * (y + b1[o])
//     Ujn[p][perm(o)] = -|w2[o]|/2 * y
// perm puts w2>=0 channels first (stable order). 128 blocks x 16 pts, 256 thr.
// ---------------------------------------------------------------------------
__global__ void k1_proj(const float* __restrict__ x,
                        const float* __restrict__ w1,
                        const float* __restrict__ b1,
                        const float* __restrict__ w2) {
    __shared__ float W1T[CH][65];                  // [c][o]
    __shared__ __align__(16) float xsT[CH][20];    // [c][p]
    __shared__ float b1s[CH];
    __shared__ float w2s[CH];

    int t = threadIdx.x;
    int p0 = blockIdx.x * 16;

#pragma unroll
    for (int q = t; q < 1024; q += 256) {
        int o = q >> 4, c4 = (q & 15) * 4;
        float4 v = reinterpret_cast<const float4*>(w1)[q];
        W1T[c4 + 0][o] = v.x;
        W1T[c4 + 1][o] = v.y;
        W1T[c4 + 2][o] = v.z;
        W1T[c4 + 3][o] = v.w;
    }
    {
        int pl = t >> 4, c4 = (t & 15) * 4;
        float4 v = reinterpret_cast<const float4*>(x + p0 * CH)[t];
        xsT[c4 + 0][pl] = v.x;
        xsT[c4 + 1][pl] = v.y;
        xsT[c4 + 2][pl] = v.z;
        xsT[c4 + 3][pl] = v.w;
    }
    if (t < CH) { b1s[t] = b1[t]; w2s[t] = w2[t]; }
    __syncthreads();

    int o = t & 63, pg = t >> 6;
    float a0 = 0.f, a1 = 0.f, a2 = 0.f, a3 = 0.f;
#pragma unroll
    for (int c = 0; c < CH; ++c) {
        float wv = W1T[c][o];
        float4 xv = *reinterpret_cast<const float4*>(&xsT[c][pg * 4]);
        a0 += wv * xv.x;
        a1 += wv * xv.y;
        a2 += wv * xv.z;
        a3 += wv * xv.w;
    }

    // Stable sign-partition permutation of channel o
    float wv = w2s[o];
    bool  sp = (wv >= 0.f);
    int cp = 0, rank = 0;
#pragma unroll
    for (int c = 0; c < CH; ++c) {
        bool p = (w2s[c] >= 0.f);
        cp += p;
        rank += (c < o) && (p == sp);
    }
    int pos = sp ? rank : cp + rank;
    if (blockIdx.x == 0 && t == 0) g_cp = cp;

    float sw  = 0.5f * fabsf(wv);
    float b1v = b1s[o];
    int pbase = p0 + pg * 4;
    g_Ui [(pbase + 0) * CH + pos] = sw * (a0 + b1v);
    g_Ujn[(pbase + 0) * CH + pos] = -sw * a0;
    g_Ui [(pbase + 1) * CH + pos] = sw * (a1 + b1v);
    g_Ujn[(pbase + 1) * CH + pos] = -sw * a1;
    g_Ui [(pbase + 2) * CH + pos] = sw * (a2 + b1v);
    g_Ujn[(pbase + 2) * CH + pos] = -sw * a2;
    g_Ui [(pbase + 3) * CH + pos] = sw * (a3 + b1v);
    g_Ujn[(pbase + 3) * CH + pos] = -sw * a3;
}

// ---------------------------------------------------------------------------
// K2: score[i,j] = rI_i + rJn_j + sum_{c<cp}|Ui+Ujn| - sum_{c>=cp}|Ui+Ujn|
// Block tile 64x64, 256 threads, 4x4 microtile. Inner op pair: FADD + FADD|.|
// Grid: (jt=16, it=16, b=2)
// ---------------------------------------------------------------------------
__global__ void k2_scores(const float* __restrict__ b2p,
                          float* __restrict__ out) {
    __shared__ __align__(16) float Uis[64][68];
    __shared__ __align__(16) float Ujs[64][68];
    __shared__ float rIs[64], rJn[64];

    int t  = threadIdx.x;
    int jt = blockIdx.x, it = blockIdx.y, b = blockIdx.z;
    int cp = g_cp;

    const float* Ui = g_Ui  + ((b * NSEQ + it * 64) * CH);
    const float* Uj = g_Ujn + ((b * NSEQ + jt * 64) * CH);

#pragma unroll
    for (int iter = 0; iter < 4; ++iter) {
        int q   = iter * 256 + t;
        int row = q >> 4, cq = (q & 15) * 4;
        float4 v = reinterpret_cast<const float4*>(Ui)[q];
        *reinterpret_cast<float4*>(&Uis[row][cq]) = v;
        float4 u = reinterpret_cast<const float4*>(Uj)[q];
        *reinterpret_cast<float4*>(&Ujs[row][cq]) = u;
    }
    __syncthreads();

    // Per-row scalars from staged tiles (sign flip at cp recovers w2h-weighted sums)
    if (t < 64) {
        float a = 0.f;
#pragma unroll 8
        for (int c = 0; c < CH; ++c) {
            float u = Uis[t][c];
            a += (c < cp) ? u : -u;
        }
        rIs[t] = a + b2p[0];
    } else if (t < 128) {
        int j = t - 64;
        float a = 0.f;
#pragma unroll 8
        for (int c = 0; c < CH; ++c) {
            float u = Ujs[j][c];
            a += (c < cp) ? u : -u;
        }
        rJn[j] = a;
    }
    __syncthreads();

    int tx = t & 15, ty = t >> 4;   // i_local = ty + 16r, j_local = tx + 16s
    float acc[4][4] = {};

    int cpc = cp >> 2;
    int rem = cp & 3;

    // Phase A: full chunks of positive-sign channels
    for (int q = 0; q < cpc; ++q) {
        int c = q * 4;
        float4 yi[4], yj[4];
#pragma unroll
        for (int r = 0; r < 4; ++r)
            yi[r] = *reinterpret_cast<const float4*>(&Uis[ty + 16 * r][c]);
#pragma unroll
        for (int s = 0; s < 4; ++s)
            yj[s] = *reinterpret_cast<const float4*>(&Ujs[tx + 16 * s][c]);
#pragma unroll
        for (int r = 0; r < 4; ++r)
#pragma unroll
            for (int s = 0; s < 4; ++s) {
                acc[r][s] += fabsf(yi[r].x + yj[s].x);
                acc[r][s] += fabsf(yi[r].y + yj[s].y);
                acc[r][s] += fabsf(yi[r].z + yj[s].z);
                acc[r][s] += fabsf(yi[r].w + yj[s].w);
            }
    }

    // Phase B: the mixed chunk (at most one)
    if (rem) {
        int c = cpc * 4;
        float s0 = (0 < rem) ? 1.f : -1.f;
        float s1 = (1 < rem) ? 1.f : -1.f;
        float s2 = (2 < rem) ? 1.f : -1.f;
        float4 yi[4], yj[4];
#pragma unroll
        for (int r = 0; r < 4; ++r)
            yi[r] = *reinterpret_cast<const float4*>(&Uis[ty + 16 * r][c]);
#pragma unroll
        for (int s = 0; s < 4; ++s)
            yj[s] = *reinterpret_cast<const float4*>(&Ujs[tx + 16 * s][c]);
#pragma unroll
        for (int r = 0; r < 4; ++r)
#pragma unroll
            for (int s = 0; s < 4; ++s) {
                acc[r][s] += s0 * fabsf(yi[r].x + yj[s].x);
                acc[r][s] += s1 * fabsf(yi[r].y + yj[s].y);
                acc[r][s] += s2 * fabsf(yi[r].z + yj[s].z);
                acc[r][s] -= fabsf(yi[r].w + yj[s].w);
            }
    }

    // Phase C: full chunks of negative-sign channels
    for (int q = cpc + (rem ? 1 : 0); q < 16; ++q) {
        int c = q * 4;
        float4 yi[4], yj[4];
#pragma unroll
        for (int r = 0; r < 4; ++r)
            yi[r] = *reinterpret_cast<const float4*>(&Uis[ty + 16 * r][c]);
#pragma unroll
        for (int s = 0; s < 4; ++s)
            yj[s] = *reinterpret_cast<const float4*>(&Ujs[tx + 16 * s][c]);
#pragma unroll
        for (int r = 0; r < 4; ++r)
#pragma unroll
            for (int s = 0; s < 4; ++s) {
                acc[r][s] -= fabsf(yi[r].x + yj[s].x);
                acc[r][s] -= fabsf(yi[r].y + yj[s].y);
                acc[r][s] -= fabsf(yi[r].z + yj[s].z);
                acc[r][s] -= fabsf(yi[r].w + yj[s].w);
            }
    }

#pragma unroll
    for (int r = 0; r < 4; ++r) {
        int ig   = it * 64 + ty + 16 * r;
        float ri = rIs[ty + 16 * r];
        float* orow = out + (size_t)(b * NSEQ + ig) * NSEQ + jt * 64;
#pragma unroll
        for (int s = 0; s < 4; ++s) {
            orow[tx + 16 * s] = ri + rJn[tx + 16 * s] + acc[r][s];
        }
    }
}

// ---------------------------------------------------------------------------
// K3: in-place row softmax over j. One block per (b,i) row. 256 threads x 4.
// ---------------------------------------------------------------------------
__global__ void k3_softmax(float* __restrict__ out) {
    __shared__ float red[8];
    __shared__ float bcast;
    size_t base = (size_t)blockIdx.x * NSEQ;
    int t = threadIdx.x;

    float v0 = out[base + t];
    float v1 = out[base + t + 256];
    float v2 = out[base + t + 512];
    float v3 = out[base + t + 768];

    float m = fmaxf(fmaxf(v0, v1), fmaxf(v2, v3));
#pragma unroll
    for (int o = 16; o; o >>= 1) m = fmaxf(m, __shfl_xor_sync(0xffffffffu, m, o));
    if ((t & 31) == 0) red[t >> 5] = m;
    __syncthreads();
    if (t == 0) {
        float mm = red[0];
#pragma unroll
        for (int i = 1; i < 8; ++i) mm = fmaxf(mm, red[i]);
        bcast = mm;
    }
    __syncthreads();
    m = bcast;

    float e0 = __expf(v0 - m), e1 = __expf(v1 - m);
    float e2 = __expf(v2 - m), e3 = __expf(v3 - m);
    float s = (e0 + e1) + (e2 + e3);
#pragma unroll
    for (int o = 16; o; o >>= 1) s += __shfl_xor_sync(0xffffffffu, s, o);
    __syncthreads();
    if ((t & 31) == 0) red[t >> 5] = s;
    __syncthreads();
    if (t == 0) {
        float ss = red[0];
#pragma unroll
        for (int i = 1; i < 8; ++i) ss += red[i];
        bcast = 1.0f / ss;
    }
    __syncthreads();
    float inv = bcast;

    out[base + t]       = e0 * inv;
    out[base + t + 256] = e1 * inv;
    out[base + t + 512] = e2 * inv;
    out[base + t + 768] = e3 * inv;
}

// ---------------------------------------------------------------------------
extern "C" void kernel_launch(void* const* d_in, const int* in_sizes, int n_in,
                              void* d_out, int out_size) {
    const float* x  = (const float*)d_in[0];  // [2,1024,64]
    const float* w1 = (const float*)d_in[1];  // [64,64]
    const float* b1 = (const float*)d_in[2];  // [64]
    const float* w2 = (const float*)d_in[3];  // [64]
    const float* b2 = (const float*)d_in[4];  // scalar
    float* out = (float*)d_out;               // [2,1024,1024]

    k1_proj<<<128, 256>>>(x, w1, b1, w2);
    dim3 g2(16, 16, 2);
    k2_scores<<<g2, 256>>>(b2, out);
    k3_softmax<<<2048, 256>>>(out);
}